// round 17
// baseline (speedup 1.0000x reference)
#include <cuda_runtime.h>
#include <math.h>

#define HH 512
#define NN 64
#define LL 4096
#define MM 2048
#define LF 2049

typedef unsigned long long ull;

__device__ float2 g_X[HH * LF];   // Cauchy spectrum X[h][l], l=0..2048
__device__ float2 g_tw[1025];     // exp(+i*pi*j/2048), j=0..1024

__device__ __forceinline__ ull f2_fma(ull a, ull b, ull c) {
    ull d; asm("fma.rn.f32x2 %0, %1, %2, %3;" : "=l"(d) : "l"(a), "l"(b), "l"(c)); return d;
}
__device__ __forceinline__ ull f2_mul(ull a, ull b) {
    ull d; asm("mul.rn.f32x2 %0, %1, %2;" : "=l"(d) : "l"(a), "l"(b)); return d;
}
__device__ __forceinline__ ull f2_add(ull a, ull b) {
    ull d; asm("add.rn.f32x2 %0, %1, %2;" : "=l"(d) : "l"(a), "l"(b)); return d;
}
__device__ __forceinline__ ull f2_pack(float lo, float hi) {
    ull d; asm("mov.b64 %0, {%1, %2};" : "=l"(d) : "f"(lo), "f"(hi)); return d;
}
__device__ __forceinline__ float2 f2_unpack(ull a) {
    float lo, hi; asm("mov.b64 {%0, %1}, %2;" : "=f"(lo), "=f"(hi) : "l"(a));
    return make_float2(lo, hi);
}
__device__ __forceinline__ float frcp(float x) {
    float r; asm("rcp.approx.f32 %0, %1;" : "=f"(r) : "f"(x)); return r;
}

// complex helpers
__device__ __forceinline__ float2 cmul(float2 a, float2 b) {
    return make_float2(a.x * b.x - a.y * b.y, a.x * b.y + a.y * b.x);
}
__device__ __forceinline__ float2 csq(float2 a) {
    return make_float2(a.x * a.x - a.y * a.y, 2.0f * a.x * a.y);
}
__device__ __forceinline__ float2 cadd(float2 a, float2 b) { return make_float2(a.x + b.x, a.y + b.y); }
__device__ __forceinline__ float2 csub(float2 a, float2 b) { return make_float2(a.x - b.x, a.y - b.y); }
__device__ __forceinline__ float2 cmuli(float2 a) { return make_float2(-a.y, a.x); }

// ============================================================================
// Kernel A: Cauchy sums. grid (HH, 4), block 128. 4 bins/thread.
// (R16-proven source, unchanged.)
// ============================================================================
__global__ __launch_bounds__(128) void s4_cauchy(
    const float* __restrict__ A_real,
    const float* __restrict__ A_imag,
    const float* __restrict__ Bm,
    const float* __restrict__ Cm,
    const float* __restrict__ Pm,
    const float* __restrict__ inv_dt)
{
    __shared__ ulonglong2 s_coef[NN / 2][9];

    const int h   = blockIdx.x;
    const int tid = threadIdx.x;

    if (blockIdx.y == 0 && blockIdx.x < 9) {
        const int j = blockIdx.x * 128 + tid;
        if (j <= 1024) {
            float s, c;
            sincosf((float)j * (3.14159265358979323846f / 2048.0f), &s, &c);
            g_tw[j] = make_float2(c, s);
        }
    }

    if (tid < NN) {
        const int n  = tid;
        const float dt = expf(inv_dt[h]);
        const float ar = -expf(A_real[h * NN + n]) * dt;
        const float ai =  A_imag[h * NN + n] * dt;

        const int base = (h * NN + n) * 2;
        const float bx = Bm[base], by = Bm[base + 1];
        const float cx = Cm[base], cy = Cm[base + 1];
        const float px = Pm[base], py = Pm[base + 1];

        float vr[4], vi[4];
        vr[0] = (bx * cx - by * cy) * dt;  vi[0] = (bx * cy + by * cx) * dt;
        vr[1] = (bx * px + by * py) * dt;  vi[1] = (by * px - bx * py) * dt;
        vr[2] = (px * cx - py * cy) * dt;  vi[2] = (px * cy + py * cx) * dt;
        vr[3] = (px * px + py * py) * dt;  vi[3] = 0.0f;

        float* c = (float*)&s_coef[n >> 1][0];
        const int o = n & 1;
        const float ccoef = -2.0f * ar;
        const float m  = ar * ar + ai * ai;
        c[0 + o] = m;                              // m
        c[2 + o] = ccoef * ccoef;                  // c^2
        #pragma unroll
        for (int ab = 0; ab < 4; ab++) {
            const float p   = -2.0f * (vr[ab] * ar + vi[ab] * ai);
            const float q   =  2.0f * vr[ab];
            const float qc  = q * ccoef;
            const float npc = -p * ccoef;
            const int bo = 4 + ab * 8;
            c[bo + 0 + o] = p * m;                 // pm
            c[bo + 2 + o] = qc - p;                // qcp
            c[bo + 4 + o] = q * m + npc;           // qmnpc
            c[bo + 6 + o] = q;                     // q
        }
    }
    __syncthreads();

    const float ANG = 3.14159265358979323846f / 4096.0f;
    const int base_l = blockIdx.y * 512 + tid;

    float yv[4];
    ull y2v[4], ny2v[4];
    #pragma unroll
    for (int b = 0; b < 4; b++) {
        const float ang = (float)(base_l + b * 128) * ANG;
        float s_, c_;
        __sincosf(ang, &s_, &c_);
        const float y = 2.0f * s_ * frcp(c_);      // fast tan (MUFU path)
        yv[b] = y;
        y2v[b]  = f2_pack(y * y, y * y);
        ny2v[b] = y2v[b] ^ 0x8000000080000000ULL;
    }

    ull accr[4][4], acci[4][4];
    #pragma unroll
    for (int b = 0; b < 4; b++)
        #pragma unroll
        for (int ab = 0; ab < 4; ab++) { accr[b][ab] = 0; acci[b][ab] = 0; }

    #pragma unroll 4
    for (int k = 0; k < NN / 2; k++) {
        const ulonglong2* cc = &s_coef[k][0];
        const ulonglong2 c0 = cc[0];               // (m, c2)

        ull invv[4];
        #pragma unroll
        for (int b = 0; b < 4; b++) {
            const ull dr  = f2_add(c0.x, ny2v[b]);                 // m - y2
            const ull mag = f2_fma(dr, dr, f2_mul(c0.y, y2v[b]));  // dr^2 + c2*y2
            const float2 m = f2_unpack(mag);
            invv[b] = f2_pack(frcp(m.x), frcp(m.y));
        }

        #pragma unroll
        for (int ab = 0; ab < 4; ab++) {
            const ulonglong2 ca = cc[1 + 2 * ab];  // (pm, qcp)
            const ulonglong2 cb = cc[2 + 2 * ab];  // (qmnpc, q)
            #pragma unroll
            for (int b = 0; b < 4; b++) {
                const ull rt  = f2_fma(y2v[b],  ca.y, ca.x);   // pm + y2*qcp
                const ull it2 = f2_fma(ny2v[b], cb.y, cb.x);   // qmnpc - y2*q
                accr[b][ab] = f2_fma(rt,  invv[b], accr[b][ab]);
                acci[b][ab] = f2_fma(it2, invv[b], acci[b][ab]);
            }
        }
    }

    #pragma unroll
    for (int b = 0; b < 4; b++) {
        const float y = yv[b];
        const int   l = base_l + b * 128;
        const float2 sr0 = f2_unpack(accr[b][0]), si0 = f2_unpack(acci[b][0]);
        const float2 sr1 = f2_unpack(accr[b][1]), si1 = f2_unpack(acci[b][1]);
        const float2 sr2 = f2_unpack(accr[b][2]), si2 = f2_unpack(acci[b][2]);
        const float2 sr3 = f2_unpack(accr[b][3]), si3 = f2_unpack(acci[b][3]);
        const float r00r = sr0.x + sr0.y, r00i = (si0.x + si0.y) * y;
        const float r01r = sr1.x + sr1.y, r01i = (si1.x + si1.y) * y;
        const float r10r = sr2.x + sr2.y, r10i = (si2.x + si2.y) * y;
        const float r11r = sr3.x + sr3.y, r11i = (si3.x + si3.y) * y;

        const float cr = 1.0f + r11r, ci = r11i;
        const float cinv = frcp(cr * cr + ci * ci);
        const float trm = r01r * r10r - r01i * r10i;
        const float tim = r01r * r10i + r01i * r10r;
        const float qr = (trm * cr + tim * ci) * cinv;
        const float qi = (tim * cr - trm * ci) * cinv;
        const float kr = r00r - qr;
        const float ki = r00i - qi;
        const float hy = 0.5f * y;
        float fr = kr - ki * hy;
        float fi = ki + kr * hy;
        if (l == 0) fi = 0.0f;
        g_X[h * LF + l] = make_float2(fr, fi);
    }

    if (blockIdx.y == 3 && tid == 0) {
        const float y  = 2.0f * tanf(2048.0f * ANG);
        const float y2 = y * y;
        float rr[4] = {0, 0, 0, 0}, riy[4] = {0, 0, 0, 0};
        for (int n = 0; n < NN; n++) {
            const float* c = (const float*)&s_coef[n >> 1][0];
            const int o = n & 1;
            const float dr = c[0 + o] - y2;
            const float inv = frcp(dr * dr + c[2 + o] * y2);
            #pragma unroll
            for (int ab = 0; ab < 4; ab++) {
                const int bo = 4 + ab * 8;
                rr[ab]  += (c[bo + 0 + o] + y2 * c[bo + 2 + o]) * inv;
                riy[ab] += (c[bo + 4 + o] - y2 * c[bo + 6 + o]) * inv;
            }
        }
        const float r00r = rr[0];
        const float r01r = rr[1], r01i = riy[1] * y;
        const float r10r = rr[2], r10i = riy[2] * y;
        const float r11r = rr[3], r11i = riy[3] * y;
        const float cr = 1.0f + r11r, ci = r11i;
        const float cinv = frcp(cr * cr + ci * ci);
        const float trm = r01r * r10r - r01i * r10i;
        const float tim = r01r * r10i + r01i * r10r;
        const float qr = (trm * cr + tim * ci) * cinv;
        const float qi = (tim * cr - trm * ci) * cinv;
        const float kr = r00r - qr;
        const float ki = riy[0] * y - qi;
        const float fr = kr - ki * (0.5f * y);
        g_X[h * LF + 2048] = make_float2(fr, 0.0f);
    }
}

// ============================================================================
// Kernel B: irfft-4096 via complex iFFT-2048. 512 threads, 4 elem/thread
// (doubles warp supply vs 256-thread radix-8 version: 43% -> 86% occ ceiling).
// Z-build + in-register radix-4 (stages 1,2), then fused radix-4 smem passes
// s=3,5,7,9 (R5-proven pass code) and final radix-2 (stage 11).
// ============================================================================
#define IDX(i) ((i) + ((i) >> 3))

__global__ __launch_bounds__(512) void s4_fft(float* __restrict__ out)
{
    __shared__ float2 buf[2305];    // X staging, then FFT workspace (aliased)
    __shared__ float2 tw[1025];

    const int h   = blockIdx.x;
    const int tid = threadIdx.x;

    // phase 0: coalesced X load into buf
    const float2* Xh = &g_X[h * LF];
    #pragma unroll
    for (int m = 0; m < 4; m++) {
        const int i = tid + m * 512;
        buf[IDX(i)] = Xh[i];
    }
    if (tid == 0) buf[IDX(2048)] = Xh[2048];
    for (int j = tid; j <= 1024; j += 512) tw[j] = g_tw[j];
    __syncthreads();

    // phase 1: gather X (bit-reversed), build Z, in-register radix-4 (stages 1,2)
    {
        const int rv = __brev(tid) >> 23;             // rev9(tid)
        float2 c[4];
        #pragma unroll
        for (int q = 0; q < 4; q++) {
            const int rq = (q == 0) ? 0 : (q == 1) ? 2 : (q == 2) ? 1 : 3;   // rev2(q)
            const int k  = rq * 512 + rv;
            const float2 Xk = buf[IDX(k)];
            const float2 Xm = buf[IDX(2048 - k)];
            float2 w;
            if (k <= 1024) w = tw[k];
            else { const float2 t = tw[k - 1024]; w = make_float2(-t.y, t.x); }
            const float arr = Xk.x + Xm.x, aii = Xk.y - Xm.y;
            const float brr = Xk.x - Xm.x, bii = Xk.y + Xm.y;
            c[q] = make_float2(arr - (w.x * bii + w.y * brr),
                               aii + (w.x * brr - w.y * bii));
        }
        // radix-4, twiddle-free (j=0): stage1 pairs (0,1),(2,3); stage2 (0,2),(1,3) w/ i
        const float2 a0 = cadd(c[0], c[1]);
        const float2 a1 = csub(c[0], c[1]);
        const float2 a2 = cadd(c[2], c[3]);
        const float2 a3 = csub(c[2], c[3]);
        const float2 ia3 = cmuli(a3);
        const float2 o0 = cadd(a0, a2);
        const float2 o2 = csub(a0, a2);
        const float2 o1 = cadd(a1, ia3);
        const float2 o3 = csub(a1, ia3);

        __syncthreads();    // everyone done READING buf before overwriting it

        const int p0 = 4 * tid;
        buf[IDX(p0 + 0)] = o0;
        buf[IDX(p0 + 1)] = o1;
        buf[IDX(p0 + 2)] = o2;
        buf[IDX(p0 + 3)] = o3;
    }
    __syncthreads();

    // fused radix-4 passes: stage pairs (3,4),(5,6),(7,8),(9,10)
    #pragma unroll
    for (int s = 3; s <= 9; s += 2) {
        const int hh = 1 << (s - 1);
        const int j  = tid & (hh - 1);
        const int bb = ((tid >> (s - 1)) << (s + 1)) + j;
        const int i0 = IDX(bb), i1 = IDX(bb + hh), i2 = IDX(bb + 2 * hh), i3 = IDX(bb + 3 * hh);

        const float2 w2 = tw[j << (11 - s)];   // W_M^(j*2^(10-s)), index <= 1020
        const float2 w1 = csq(w2);

        const float2 x0 = buf[i0], x1 = buf[i1], x2 = buf[i2], x3 = buf[i3];

        const float2 t1 = cmul(w1, x1);
        const float2 a0 = cadd(x0, t1), a1 = csub(x0, t1);
        const float2 t3 = cmul(w1, x3);
        const float2 a2 = cadd(x2, t3), a3 = csub(x2, t3);

        const float2 t2 = cmul(w2, a2);
        const float2 c3 = cmuli(cmul(w2, a3));

        buf[i0] = cadd(a0, t2);
        buf[i2] = csub(a0, t2);
        buf[i1] = cadd(a1, c3);
        buf[i3] = csub(a1, c3);
        __syncthreads();
    }

    // final radix-2 stage (11): 1024 butterflies, 2 per thread
    #pragma unroll
    for (int m = 0; m < 2; m++) {
        const int j = tid + m * 512;
        float2 w;
        const int t = 2 * j;
        if (t <= 1024) w = tw[t];
        else { const float2 u = tw[t - 1024]; w = make_float2(-u.y, u.x); }
        const float2 a = buf[IDX(j)];
        const float2 b = buf[IDX(j + 1024)];
        const float trr = w.x * b.x - w.y * b.y;
        const float tii = w.x * b.y + w.y * b.x;
        buf[IDX(j)]        = make_float2(a.x + trr, a.y + tii);
        buf[IDX(j + 1024)] = make_float2(a.x - trr, a.y - tii);
    }
    __syncthreads();

    // unpack: out[h][2n] = Re(z[n])/L, out[h][2n+1] = Im(z[n])/L
    float2* out2 = (float2*)(out + h * LL);
    const float scale = 1.0f / (float)LL;
    #pragma unroll
    for (int m = 0; m < 4; m++) {
        const int n = tid + m * 512;
        const float2 z = buf[IDX(n)];
        out2[n] = make_float2(z.x * scale, z.y * scale);
    }
}

extern "C" void kernel_launch(void* const* d_in, const int* in_sizes, int n_in,
                              void* d_out, int out_size)
{
    (void)in_sizes; (void)n_in; (void)out_size;
    dim3 gridA(HH, 4);
    s4_cauchy<<<gridA, 128>>>(
        (const float*)d_in[0],   // A_real (H, N)
        (const float*)d_in[1],   // A_imag (H, N)
        (const float*)d_in[2],   // B (1, H, N, 2)
        (const float*)d_in[3],   // C (1, H, N, 2)
        (const float*)d_in[4],   // P (1, H, N, 2)
        (const float*)d_in[5]);  // inv_dt (H,)
    s4_fft<<<HH, 512>>>((float*)d_out);
}